// round 5
// baseline (speedup 1.0000x reference)
#include <cuda_runtime.h>
#include <math.h>

#define Bsz    2048
#define Hd     256
#define INd    64
#define KTERMS 8
#define ROWS   14            // batch rows per CTA (7 f32x2 pairs)
#define NCTAS  147
#define PITCH  20            // smem row pitch in floats (80B)
#define NTHR   512

typedef unsigned long long ull;

// Pre-transposed weights (L2-resident)
__device__ float g_whT[Hd*Hd];     // whT[j*Hd+k]   = wh[k*Hd+j]
__device__ float g_woutT[Hd*Hd];   // woutT[j*Hd+k] = wout[k*Hd+j]
__device__ float g_wxT[INd*Hd];    // wxT[i*Hd+k]   = wx[k*INd+i]

// ---------------- packed f32x2 helpers ----------------
__device__ __forceinline__ ull pack2(float lo, float hi) {
    ull r; asm("mov.b64 %0, {%1,%2};" : "=l"(r) : "f"(lo), "f"(hi)); return r;
}
__device__ __forceinline__ void unpack2(ull v, float& lo, float& hi) {
    asm("mov.b64 {%0,%1}, %2;" : "=f"(lo), "=f"(hi) : "l"(v));
}
__device__ __forceinline__ ull fma2(ull a, ull b, ull c) {
    ull d; asm("fma.rn.f32x2 %0, %1, %2, %3;" : "=l"(d) : "l"(a), "l"(b), "l"(c)); return d;
}
__device__ __forceinline__ ull mul2(ull a, ull b) {
    ull d; asm("mul.rn.f32x2 %0, %1, %2;" : "=l"(d) : "l"(a), "l"(b)); return d;
}
__device__ __forceinline__ ull add2(ull a, ull b) {
    ull d; asm("add.rn.f32x2 %0, %1, %2;" : "=l"(d) : "l"(a), "l"(b)); return d;
}
__device__ __forceinline__ ull shx64(ull v, int m) {
    return __shfl_xor_sync(0xFFFFFFFFu, v, m);
}

struct Row { ull v[7]; };
__device__ __forceinline__ Row ldrow(const float* p) {
    Row r;
    const ulonglong2* q = reinterpret_cast<const ulonglong2*>(p);
    ulonglong2 a = q[0], b = q[1], c = q[2];
    r.v[0]=a.x; r.v[1]=a.y; r.v[2]=b.x; r.v[3]=b.y; r.v[4]=c.x; r.v[5]=c.y;
    r.v[6] = reinterpret_cast<const ull*>(p)[6];
    return r;
}

// physical row permutation: quad lanes (g=0..3) land on ADJACENT physical rows
__device__ __forceinline__ int physH(int j) { return ((j & 63) << 2) + (j >> 6); }   // 256 rows
__device__ __forceinline__ int physX(int i) { return ((i & 15) << 2) + (i >> 4); }   // 64 rows

// dual-column partial GEMM over this lane's j-quarter
__device__ __forceinline__ void gemm2(const float* __restrict__ Wt, int col0, int g,
                                      const float* sIn, ull accA[7], ull accB[7]) {
    const float* wp = Wt + (g * 64) * Hd;
    const float* sp = sIn + g * PITCH;          // phys row jj*4+g
#pragma unroll 8
    for (int jj = 0; jj < 64; ++jj) {
        float wa = wp[col0];
        float wb = wp[col0 + 128];
        ull wwa = pack2(wa, wa), wwb = pack2(wb, wb);
        Row v = ldrow(sp);
#pragma unroll
        for (int q = 0; q < 7; ++q) {
            accA[q] = fma2(wwa, v.v[q], accA[q]);
            accB[q] = fma2(wwb, v.v[q], accB[q]);
        }
        wp += Hd;
        sp += 4 * PITCH;
    }
}

// merge partials across the quad. After: lanes g<2 get full column-A sum in m,
// lanes g>=2 get full column-B sum in m.
__device__ __forceinline__ void merge_cross(const ull accA[7], const ull accB[7],
                                            bool lowg, ull m[7]) {
#pragma unroll
    for (int q = 0; q < 7; ++q) {
        ull a = add2(accA[q], shx64(accA[q], 1));
        ull b = add2(accB[q], shx64(accB[q], 1));
        ull s = lowg ? b : a;
        s = shx64(s, 2);
        m[q] = add2(lowg ? a : b, s);
    }
}

// the two lanes owning a column split the 7-u64 row store (ghalf = g&1)
__device__ __forceinline__ void strow_split(float* base, int phys, int ghalf, const ull v[7]) {
    ull* p = reinterpret_cast<ull*>(base + phys * PITCH);
    if (ghalf == 0) {
        reinterpret_cast<ulonglong2*>(p)[0] = make_ulonglong2(v[0], v[1]);
        reinterpret_cast<ulonglong2*>(p)[1] = make_ulonglong2(v[2], v[3]);
    } else {
        reinterpret_cast<ulonglong2*>(p)[2] = make_ulonglong2(v[4], v[5]);
        p[6] = v[6];
    }
}

// ---------------- merged transpose ----------------
__global__ void transpose_all(const float* __restrict__ wh,
                              const float* __restrict__ wout,
                              const float* __restrict__ wx) {
    __shared__ float tile[32][33];
    int b = blockIdx.x;
    const float* in; float* out; int rows, cols, bx;
    if (b < 64)       { in = wh;   out = g_whT;   rows = Hd; cols = Hd;  bx = b; }
    else if (b < 128) { in = wout; out = g_woutT; rows = Hd; cols = Hd;  bx = b - 64; }
    else              { in = wx;   out = g_wxT;   rows = Hd; cols = INd; bx = b - 128; }
    int nbx = cols / 32;
    int c0 = (bx % nbx) * 32, r0 = (bx / nbx) * 32;
    for (int dy = threadIdx.y; dy < 32; dy += 8)
        tile[dy][threadIdx.x] = in[(r0 + dy) * cols + (c0 + threadIdx.x)];
    __syncthreads();
    for (int dy = threadIdx.y; dy < 32; dy += 8)
        out[(c0 + dy) * rows + (r0 + threadIdx.x)] = tile[threadIdx.x][dy];
}

// ---------------- fused vector-field kernel ----------------
__global__ void __launch_bounds__(NTHR, 1)
fused_kernel(const float* __restrict__ hin, const float* __restrict__ xin,
             const float* __restrict__ xdin, const float* __restrict__ b0,
             const float* __restrict__ b1, float* __restrict__ out) {
    __shared__ __align__(16) float sA[Hd * PITCH];   // 20KB
    __shared__ __align__(16) float sB[Hd * PITCH];   // 20KB

    const int tid  = threadIdx.x;
    const int g    = tid & 3;          // j-quarter, lanes of a quad
    const int c0   = tid >> 2;         // column pair base (0..127)
    const bool lowg = (g < 2);
    const int ghalf = g & 1;
    const int mycol = lowg ? c0 : (c0 + 128);
    const int myphys = physH(mycol);
    const int row0 = blockIdx.x * ROWS;

    // ---- stage inputs (transposed + row-permuted)
    for (int e = tid; e < ROWS * Hd; e += NTHR) {
        int r = e >> 8, j = e & 255;
        sA[physH(j) * PITCH + r] = (row0 + r < Bsz) ? hin[(row0 + r) * Hd + j] : 0.f;
    }
    for (int e = tid; e < ROWS * INd; e += NTHR) {
        int r = e >> 6, i = e & 63;
        bool ok = (row0 + r < Bsz);
        int p = physX(i);
        sB[p * PITCH + r]          = ok ? xin[(row0 + r) * INd + i]  : 0.f;
        sB[(INd + p) * PITCH + r]  = ok ? xdin[(row0 + r) * INd + i] : 0.f;
    }
    __syncthreads();

    // ---- phase 1 partials: l1 = x@wx^T + h@wh^T ; uu = xdot@wx^T
    ull l1a[7], l1b[7], ua[7], ub[7];
#pragma unroll
    for (int q = 0; q < 7; ++q) { l1a[q]=0; l1b[q]=0; ua[q]=0; ub[q]=0; }
    {
        const float* wp  = g_wxT + (g * 16) * Hd;
        const float* spx = sB + g * PITCH;                // x rows: phys ii*4+g
        const float* spd = sB + (INd + g) * PITCH;        // xdot rows
#pragma unroll 4
        for (int ii = 0; ii < 16; ++ii) {
            float wa = wp[c0];
            float wb = wp[c0 + 128];
            ull wwa = pack2(wa, wa), wwb = pack2(wb, wb);
            Row vx = ldrow(spx);
            Row vd = ldrow(spd);
#pragma unroll
            for (int q = 0; q < 7; ++q) {
                l1a[q] = fma2(wwa, vx.v[q], l1a[q]);
                l1b[q] = fma2(wwb, vx.v[q], l1b[q]);
                ua[q]  = fma2(wwa, vd.v[q], ua[q]);
                ub[q]  = fma2(wwb, vd.v[q], ub[q]);
            }
            wp += Hd; spx += 4 * PITCH; spd += 4 * PITCH;
        }
    }
    gemm2(g_whT, c0, g, sA, l1a, l1b);   // + h @ wh^T
    __syncthreads();                     // all smem reads of phase 1 done

    // merge l1 -> gate + relu; merge uu -> gated u
    ull gate[7], dth[7], hdot[7];
    {
        ull m[7];
        merge_cross(l1a, l1b, lowg, m);
        float bk = b0[mycol];
        ull bp = pack2(bk, bk);
        ull relu[7];
#pragma unroll
        for (int q = 0; q < 7; ++q) {
            m[q] = add2(m[q], bp);
            float a, bb; unpack2(m[q], a, bb);
            float ga = (a  > 0.f) ? 1.f : 0.f;
            float gb = (bb > 0.f) ? 1.f : 0.f;
            gate[q] = pack2(ga, gb);
            relu[q] = pack2(ga * a, gb * bb);
        }
        strow_split(sB, myphys, ghalf, relu);
        ull mu[7];
        merge_cross(ua, ub, lowg, mu);
        ull gu[7];
#pragma unroll
        for (int q = 0; q < 7; ++q) gu[q] = mul2(mu[q], gate[q]);
        strow_split(sA, myphys, ghalf, gu);
    }
    __syncthreads();

    // ---- phase 2 partials: lout = relu@wout^T ; jx = (g*u)@wout^T
    ull loa[7], lob[7], jxa[7], jxb[7];
#pragma unroll
    for (int q = 0; q < 7; ++q) { loa[q]=0; lob[q]=0; jxa[q]=0; jxb[q]=0; }
    {
        const float* wp  = g_woutT + (g * 64) * Hd;
        const float* spr = sB + g * PITCH;
        const float* spg = sA + g * PITCH;
#pragma unroll 4
        for (int jj = 0; jj < 64; ++jj) {
            float wa = wp[c0];
            float wb = wp[c0 + 128];
            ull wwa = pack2(wa, wa), wwb = pack2(wb, wb);
            Row vr = ldrow(spr);
            Row vg = ldrow(spg);
#pragma unroll
            for (int q = 0; q < 7; ++q) {
                loa[q] = fma2(wwa, vr.v[q], loa[q]);
                lob[q] = fma2(wwb, vr.v[q], lob[q]);
                jxa[q] = fma2(wwa, vg.v[q], jxa[q]);
                jxb[q] = fma2(wwb, vg.v[q], jxb[q]);
            }
            wp += Hd; spr += 4 * PITCH; spg += 4 * PITCH;
        }
    }
    __syncthreads();                     // phase 2 reads done
    {
        ull m[7];
        merge_cross(loa, lob, lowg, m);
        float bk = b1[mycol];
        ull bp = pack2(bk, bk);
#pragma unroll
        for (int q = 0; q < 7; ++q) {
            ull L = add2(m[q], bp);
            float a, bb; unpack2(L, a, bb);
            float ta = tanhf(a), tb = tanhf(bb);
            dth[q] = pack2(1.f - ta * ta, 1.f - tb * tb);
        }
        ull mj[7];
        merge_cross(jxa, jxb, lowg, mj);
        ull cur[7];
#pragma unroll
        for (int q = 0; q < 7; ++q) {
            cur[q] = mul2(mj[q], dth[q]);
            hdot[q] = cur[q];
        }
        strow_split(sA, myphys, ghalf, cur);
    }
    __syncthreads();

    // ---- 8 Jh-power iterations: curr = dtanh * ((gate * (curr@wh^T)) @ wout^T)
    for (int it = 0; it < KTERMS; ++it) {
        ull accA[7], accB[7];
#pragma unroll
        for (int q = 0; q < 7; ++q) { accA[q]=0; accB[q]=0; }
        gemm2(g_whT, c0, g, sA, accA, accB);
        {
            ull m[7];
            merge_cross(accA, accB, lowg, m);
            ull gt[7];
#pragma unroll
            for (int q = 0; q < 7; ++q) gt[q] = mul2(m[q], gate[q]);
            strow_split(sB, myphys, ghalf, gt);   // writes sB: prev sB reads fenced
        }
        __syncthreads();
#pragma unroll
        for (int q = 0; q < 7; ++q) { accA[q]=0; accB[q]=0; }
        gemm2(g_woutT, c0, g, sB, accA, accB);
        {
            ull m[7];
            merge_cross(accA, accB, lowg, m);
            ull cur[7];
#pragma unroll
            for (int q = 0; q < 7; ++q) {
                cur[q] = mul2(m[q], dth[q]);
                hdot[q] = add2(hdot[q], cur[q]);
            }
            strow_split(sA, myphys, ghalf, cur);  // all warps past mid-sync => sA reads done
        }
        __syncthreads();
    }

    // ---- write h_dot: the two lanes of each column split the 7 q's
#pragma unroll
    for (int q = 0; q < 7; ++q) {
        if ((q < 4) == (ghalf == 0)) {
            float a, bb; unpack2(hdot[q], a, bb);
            int r = row0 + 2 * q;
            if (r < Bsz)     out[r       * Hd + mycol] = a;
            if (r + 1 < Bsz) out[(r + 1) * Hd + mycol] = bb;
        }
    }
}

extern "C" void kernel_launch(void* const* d_in, const int* in_sizes, int n_in,
                              void* d_out, int out_size) {
    (void)in_sizes; (void)n_in; (void)out_size;
    const float* h_   = (const float*)d_in[0];
    const float* x    = (const float*)d_in[1];
    const float* xdot = (const float*)d_in[2];
    const float* wx   = (const float*)d_in[3];
    const float* wh   = (const float*)d_in[4];
    const float* wout = (const float*)d_in[5];
    const float* b0   = (const float*)d_in[6];
    const float* b1   = (const float*)d_in[7];
    float* out = (float*)d_out;

    transpose_all<<<144, dim3(32, 8)>>>(wh, wout, wx);
    fused_kernel<<<NCTAS, NTHR>>>(h_, x, xdot, b0, b1, out);
}

// round 6
// speedup vs baseline: 1.7590x; 1.7590x over previous
#include <cuda_runtime.h>
#include <math.h>

#define Bsz    2048
#define Hd     256
#define INd    64
#define KTERMS 8
#define ROWS   14
#define NCTAS  147
#define PITCH  20          // floats per smem row (80B)
#define SLOT   34          // u64 per sRed slot (272B; stride 68 banks == 4 mod 32)
#define NTHR   512

typedef unsigned long long ull;

// Pre-transposed weights (L2-resident)
__device__ float g_whT[Hd*Hd];     // whT[j*Hd+k]   = wh[k*Hd+j]
__device__ float g_woutT[Hd*Hd];   // woutT[j*Hd+k] = wout[k*Hd+j]
__device__ float g_wxT[INd*Hd];    // wxT[i*Hd+k]   = wx[k*INd+i]

// ---------------- packed f32x2 helpers ----------------
__device__ __forceinline__ ull pack2(float lo, float hi) {
    ull r; asm("mov.b64 %0, {%1,%2};" : "=l"(r) : "f"(lo), "f"(hi)); return r;
}
__device__ __forceinline__ void unpack2(ull v, float& lo, float& hi) {
    asm("mov.b64 {%0,%1}, %2;" : "=f"(lo), "=f"(hi) : "l"(v));
}
__device__ __forceinline__ ull fma2(ull a, ull b, ull c) {
    ull d; asm("fma.rn.f32x2 %0, %1, %2, %3;" : "=l"(d) : "l"(a), "l"(b), "l"(c)); return d;
}
__device__ __forceinline__ ull mul2(ull a, ull b) {
    ull d; asm("mul.rn.f32x2 %0, %1, %2;" : "=l"(d) : "l"(a), "l"(b)); return d;
}
__device__ __forceinline__ ull add2(ull a, ull b) {
    ull d; asm("add.rn.f32x2 %0, %1, %2;" : "=l"(d) : "l"(a), "l"(b)); return d;
}

struct Row7 { ull v[7]; };
__device__ __forceinline__ Row7 ldrow(const float* p) {
    Row7 r;
    const ulonglong2* q = reinterpret_cast<const ulonglong2*>(p);
    ulonglong2 a = q[0], b = q[1], c = q[2];
    r.v[0]=a.x; r.v[1]=a.y; r.v[2]=b.x; r.v[3]=b.y; r.v[4]=c.x; r.v[5]=c.y;
    r.v[6] = reinterpret_cast<const ull*>(p)[6];
    return r;
}

// C=4 partial GEMM: acc[c*7+q] += Wt[j][col0+c] * sIn[phys(j)][2q..2q+1]
// phys(j) = (j>>2) + (j&3)*Q ; j in [j0, j0+NJ)
template<int NJ, int Q>
__device__ __forceinline__ void gemmC4(const float* __restrict__ Wt, int col0, int j0,
                                       const float* sIn, ull acc[28]) {
#pragma unroll 8
    for (int jj = 0; jj < NJ; ++jj) {
        int j = j0 + jj;
        float4 w4 = *reinterpret_cast<const float4*>(Wt + j * Hd + col0);
        int pr = (j >> 2) + (j & 3) * Q;
        Row7 v = ldrow(sIn + pr * PITCH);
        ull w0 = pack2(w4.x, w4.x), w1 = pack2(w4.y, w4.y);
        ull w2 = pack2(w4.z, w4.z), w3 = pack2(w4.w, w4.w);
#pragma unroll
        for (int q = 0; q < 7; ++q) {
            acc[q]      = fma2(w0, v.v[q], acc[q]);
            acc[7+q]    = fma2(w1, v.v[q], acc[7+q]);
            acc[14+q]   = fma2(w2, v.v[q], acc[14+q]);
            acc[21+q]   = fma2(w3, v.v[q], acc[21+q]);
        }
    }
}

// export acc[28] -> slot (padded to 8 u64 per col for aligned merge reads)
__device__ __forceinline__ void exportP(ull* p, const ull acc[28]) {
#pragma unroll
    for (int c = 0; c < 4; ++c) {
        ulonglong2* q = reinterpret_cast<ulonglong2*>(p + c * 8);
        q[0] = make_ulonglong2(acc[c*7+0], acc[c*7+1]);
        q[1] = make_ulonglong2(acc[c*7+2], acc[c*7+3]);
        q[2] = make_ulonglong2(acc[c*7+4], acc[c*7+5]);
        q[3] = make_ulonglong2(acc[c*7+6], 0ull);
    }
}

// merge slice (moff) of this quad across all 8 groups
__device__ __forceinline__ void mergeP(const ull* sRed, int quad, int moff, int half, ull m[4]) {
    m[0] = m[1] = m[2] = m[3] = 0ull;
#pragma unroll
    for (int gp = 0; gp < 8; ++gp) {
        const ull* p = sRed + (gp * 64 + quad) * SLOT + moff;
        ulonglong2 a = reinterpret_cast<const ulonglong2*>(p)[0];
        m[0] = add2(m[0], a.x);
        m[1] = add2(m[1], a.y);
        if (half == 0) {
            ulonglong2 b = reinterpret_cast<const ulonglong2*>(p)[1];
            m[2] = add2(m[2], b.x);
            m[3] = add2(m[3], b.y);
        } else {
            m[2] = add2(m[2], p[2]);
        }
    }
}

// store slice to row (half 0: u64 0..3, half 1: u64 4..6)
__device__ __forceinline__ void st_slice(float* rowbase, int half, const ull m[4]) {
    ull* p = reinterpret_cast<ull*>(rowbase) + half * 4;
    reinterpret_cast<ulonglong2*>(p)[0] = make_ulonglong2(m[0], m[1]);
    if (half == 0) reinterpret_cast<ulonglong2*>(p)[1] = make_ulonglong2(m[2], m[3]);
    else           p[2] = m[2];
}

// ---------------- merged transpose ----------------
__global__ void transpose_all(const float* __restrict__ wh,
                              const float* __restrict__ wout,
                              const float* __restrict__ wx) {
    __shared__ float tile[32][33];
    int b = blockIdx.x;
    const float* in; float* out; int rows, cols, bx;
    if (b < 64)       { in = wh;   out = g_whT;   rows = Hd; cols = Hd;  bx = b; }
    else if (b < 128) { in = wout; out = g_woutT; rows = Hd; cols = Hd;  bx = b - 64; }
    else              { in = wx;   out = g_wxT;   rows = Hd; cols = INd; bx = b - 128; }
    int nbx = cols / 32;
    int c0 = (bx % nbx) * 32, r0 = (bx / nbx) * 32;
    for (int dy = threadIdx.y; dy < 32; dy += 8)
        tile[dy][threadIdx.x] = in[(r0 + dy) * cols + (c0 + threadIdx.x)];
    __syncthreads();
    for (int dy = threadIdx.y; dy < 32; dy += 8)
        out[(c0 + dy) * rows + (r0 + threadIdx.x)] = tile[threadIdx.x][dy];
}

// ---------------- fused vector-field kernel ----------------
__global__ void __launch_bounds__(NTHR, 1)
fused_kernel(const float* __restrict__ hin, const float* __restrict__ xin,
             const float* __restrict__ xdin, const float* __restrict__ b0,
             const float* __restrict__ b1, float* __restrict__ out) {
    extern __shared__ __align__(16) char smraw[];
    float* sA   = reinterpret_cast<float*>(smraw);       // [256][PITCH]
    float* sB   = sA + Hd * PITCH;                       // [256][PITCH]
    float* sX   = sB + Hd * PITCH;                       // [128][PITCH] x | xdot
    ull*   sRed = reinterpret_cast<ull*>(sX + 128 * PITCH);  // [512][SLOT]

    const int tid   = threadIdx.x;
    const int warp  = tid >> 5;
    const int lane  = tid & 31;
    const int g     = warp >> 1;                 // j-group 0..7 (uniform per warp)
    const int quad  = ((warp & 1) << 5) + lane;  // 0..63
    const int col0  = quad << 2;
    const int cIdx  = g & 3;
    const int half  = g >> 2;
    const int mycol = col0 + cIdx;
    const int myrow = quad + cIdx * 64;          // physH(mycol)
    const int slot  = (g * 64 + quad) * SLOT;
    const int moff  = cIdx * 8 + half * 4;
    const int row0  = blockIdx.x * ROWS;

    // ---- stage inputs (transposed + phys-permuted)
    for (int e = tid; e < ROWS * Hd; e += NTHR) {
        int r = e >> 8, j = e & 255;
        int pr = (j >> 2) + (j & 3) * 64;
        sA[pr * PITCH + r] = (row0 + r < Bsz) ? hin[(row0 + r) * Hd + j] : 0.f;
    }
    for (int e = tid; e < ROWS * INd; e += NTHR) {
        int r = e >> 6, i = e & 63;
        bool ok = (row0 + r < Bsz);
        int pr = (i >> 2) + (i & 3) * 16;
        sX[pr * PITCH + r]        = ok ? xin[(row0 + r) * INd + i]  : 0.f;
        sX[(64 + pr) * PITCH + r] = ok ? xdin[(row0 + r) * INd + i] : 0.f;
    }
    __syncthreads();

    ull gate[4], dth[4], hd[4];
    ull acc[28];

    // ---- l1 = x@wxT + h@whT (+b0 at merge)
#pragma unroll
    for (int q = 0; q < 28; ++q) acc[q] = 0ull;
    gemmC4<8, 16>(g_wxT, col0, 8 * g, sX, acc);
    gemmC4<32, 64>(g_whT, col0, 32 * g, sA, acc);
    exportP(sRed + slot, acc);
    __syncthreads();
    {
        ull m[4];
        mergeP(sRed, quad, moff, half, m);
        float bk = b0[mycol];
        ull bp = pack2(bk, bk);
        ull relu[4];
#pragma unroll
        for (int t = 0; t < 4; ++t) {
            m[t] = add2(m[t], bp);
            float a, b; unpack2(m[t], a, b);
            float ga = (a > 0.f) ? 1.f : 0.f;
            float gb = (b > 0.f) ? 1.f : 0.f;
            gate[t] = pack2(ga, gb);
            relu[t] = pack2(ga * a, gb * b);
        }
        st_slice(sB + myrow * PITCH, half, relu);
    }
    __syncthreads();

    // ---- uu = xdot@wxT ; gated-u = gate*uu -> sA
#pragma unroll
    for (int q = 0; q < 28; ++q) acc[q] = 0ull;
    gemmC4<8, 16>(g_wxT, col0, 8 * g, sX + 64 * PITCH, acc);
    exportP(sRed + slot, acc);
    __syncthreads();
    {
        ull m[4];
        mergeP(sRed, quad, moff, half, m);
#pragma unroll
        for (int t = 0; t < 4; ++t) m[t] = mul2(m[t], gate[t]);
        st_slice(sA + myrow * PITCH, half, m);
    }
    __syncthreads();

    // ---- lout = relu@woutT (+b1) -> dth
#pragma unroll
    for (int q = 0; q < 28; ++q) acc[q] = 0ull;
    gemmC4<32, 64>(g_woutT, col0, 32 * g, sB, acc);
    exportP(sRed + slot, acc);
    __syncthreads();
    {
        ull m[4];
        mergeP(sRed, quad, moff, half, m);
        float bk = b1[mycol];
        ull bp = pack2(bk, bk);
#pragma unroll
        for (int t = 0; t < 4; ++t) {
            ull L = add2(m[t], bp);
            float a, b; unpack2(L, a, b);
            float ta = tanhf(a), tb = tanhf(b);
            dth[t] = pack2(1.f - ta * ta, 1.f - tb * tb);
        }
    }
    __syncthreads();

    // ---- jx = gated-u@woutT ; curr = dth*jx -> sA ; hdot = curr
#pragma unroll
    for (int q = 0; q < 28; ++q) acc[q] = 0ull;
    gemmC4<32, 64>(g_woutT, col0, 32 * g, sA, acc);
    exportP(sRed + slot, acc);
    __syncthreads();
    {
        ull m[4];
        mergeP(sRed, quad, moff, half, m);
#pragma unroll
        for (int t = 0; t < 4; ++t) {
            m[t] = mul2(m[t], dth[t]);
            hd[t] = m[t];
        }
        st_slice(sA + myrow * PITCH, half, m);
    }
    __syncthreads();

    // ---- 8 Jh-power iterations: curr = dth * ((gate * (curr@whT)) @ woutT)
    for (int it = 0; it < KTERMS; ++it) {
#pragma unroll
        for (int q = 0; q < 28; ++q) acc[q] = 0ull;
        gemmC4<32, 64>(g_whT, col0, 32 * g, sA, acc);
        exportP(sRed + slot, acc);
        __syncthreads();
        {
            ull m[4];
            mergeP(sRed, quad, moff, half, m);
#pragma unroll
            for (int t = 0; t < 4; ++t) m[t] = mul2(m[t], gate[t]);
            st_slice(sB + myrow * PITCH, half, m);
        }
        __syncthreads();
#pragma unroll
        for (int q = 0; q < 28; ++q) acc[q] = 0ull;
        gemmC4<32, 64>(g_woutT, col0, 32 * g, sB, acc);
        exportP(sRed + slot, acc);
        __syncthreads();
        {
            ull m[4];
            mergeP(sRed, quad, moff, half, m);
#pragma unroll
            for (int t = 0; t < 4; ++t) {
                m[t] = mul2(m[t], dth[t]);
                hd[t] = add2(hd[t], m[t]);
            }
            st_slice(sA + myrow * PITCH, half, m);
        }
        __syncthreads();
    }

    // ---- write h_dot slice (mycol, rows half*8 .. half*8+7/5)
#pragma unroll
    for (int t = 0; t < 4; ++t) {
        if (half == 1 && t == 3) break;
        float a, b; unpack2(hd[t], a, b);
        int r = row0 + half * 8 + 2 * t;
        if (r < Bsz)     out[r       * Hd + mycol] = a;
        if (r + 1 < Bsz) out[(r + 1) * Hd + mycol] = b;
    }
}

#define SMEM_BYTES ((2 * Hd * PITCH + 128 * PITCH) * 4 + 512 * SLOT * 8)

extern "C" void kernel_launch(void* const* d_in, const int* in_sizes, int n_in,
                              void* d_out, int out_size) {
    (void)in_sizes; (void)n_in; (void)out_size;
    const float* h_   = (const float*)d_in[0];
    const float* x    = (const float*)d_in[1];
    const float* xdot = (const float*)d_in[2];
    const float* wx   = (const float*)d_in[3];
    const float* wh   = (const float*)d_in[4];
    const float* wout = (const float*)d_in[5];
    const float* b0   = (const float*)d_in[6];
    const float* b1   = (const float*)d_in[7];
    float* out = (float*)d_out;

    cudaFuncSetAttribute(fused_kernel, cudaFuncAttributeMaxDynamicSharedMemorySize, SMEM_BYTES);
    transpose_all<<<144, dim3(32, 8)>>>(wh, wout, wx);
    fused_kernel<<<NCTAS, NTHR, SMEM_BYTES>>>(h_, x, xdot, b0, b1, out);
}

// round 7
// speedup vs baseline: 1.9795x; 1.1254x over previous
#include <cuda_runtime.h>
#include <math.h>

#define Bsz    2048
#define Hd     256
#define INd    64
#define KTERMS 8
#define ROWS   8
#define NCTAS  256
#define NTHR   256
#define PITCH  12          // floats per smem row (48B; 16B-granule stride 3 = odd -> conflict-free)
#define SLOT   18          // u64 per export slot (144B; 16B-granule stride 9 = odd -> conflict-free)

typedef unsigned long long ull;

// Pre-transposed weights (L2-resident)
__device__ float g_whT[Hd*Hd];     // whT[j*Hd+k]   = wh[k*Hd+j]
__device__ float g_woutT[Hd*Hd];   // woutT[j*Hd+k] = wout[k*Hd+j]
__device__ float g_wxT[INd*Hd];    // wxT[i*Hd+k]   = wx[k*INd+i]

// ---------------- packed f32x2 helpers ----------------
__device__ __forceinline__ ull pack2(float lo, float hi) {
    ull r; asm("mov.b64 %0, {%1,%2};" : "=l"(r) : "f"(lo), "f"(hi)); return r;
}
__device__ __forceinline__ void unpack2(ull v, float& lo, float& hi) {
    asm("mov.b64 {%0,%1}, %2;" : "=f"(lo), "=f"(hi) : "l"(v));
}
__device__ __forceinline__ ull fma2(ull a, ull b, ull c) {
    ull d; asm("fma.rn.f32x2 %0, %1, %2, %3;" : "=l"(d) : "l"(a), "l"(b), "l"(c)); return d;
}
__device__ __forceinline__ ull mul2(ull a, ull b) {
    ull d; asm("mul.rn.f32x2 %0, %1, %2;" : "=l"(d) : "l"(a), "l"(b)); return d;
}
__device__ __forceinline__ ull add2(ull a, ull b) {
    ull d; asm("add.rn.f32x2 %0, %1, %2;" : "=l"(d) : "l"(a), "l"(b)); return d;
}

struct Row4 { ull v[4]; };
__device__ __forceinline__ Row4 ldrow4(const float* p) {
    Row4 r;
    const ulonglong2* q = reinterpret_cast<const ulonglong2*>(p);
    ulonglong2 a = q[0], b = q[1];
    r.v[0]=a.x; r.v[1]=a.y; r.v[2]=b.x; r.v[3]=b.y;
    return r;
}

// C=4 partial GEMM for j-group g. acc[c*4+t] += Wt[j][col0+c] * sIn[pr(j)][t]
// j = 4*NJ4*g + jm + 4*jd ; pr(j) = (j>>2) + (j&3)*Q = NJ4*g + jm*Q + jd
// Pointer-increment only in inner loop (alu-lean).
template<int NJ4, int Q>
__device__ __forceinline__ void gemmC4(const float* __restrict__ Wt, int col0, int g,
                                       const float* sIn, ull acc[16]) {
#pragma unroll
    for (int jm = 0; jm < 4; ++jm) {
        const float* wp = Wt + (4 * NJ4 * g + jm) * Hd + col0;
        const float* sp = sIn + (NJ4 * g + jm * Q) * PITCH;
#pragma unroll
        for (int jd = 0; jd < NJ4; ++jd) {
            float4 w4 = *reinterpret_cast<const float4*>(wp);
            Row4 v = ldrow4(sp);
            ull w0 = pack2(w4.x, w4.x), w1 = pack2(w4.y, w4.y);
            ull w2 = pack2(w4.z, w4.z), w3 = pack2(w4.w, w4.w);
#pragma unroll
            for (int t = 0; t < 4; ++t) {
                acc[t]      = fma2(w0, v.v[t], acc[t]);
                acc[4+t]    = fma2(w1, v.v[t], acc[4+t]);
                acc[8+t]    = fma2(w2, v.v[t], acc[8+t]);
                acc[12+t]   = fma2(w3, v.v[t], acc[12+t]);
            }
            wp += 4 * Hd;
            sp += PITCH;
        }
    }
}

// export 16 u64 to this thread's slot (8 STS.128, conflict-free)
__device__ __forceinline__ void exportP(ull* p, const ull acc[16]) {
    ulonglong2* q = reinterpret_cast<ulonglong2*>(p);
#pragma unroll
    for (int c = 0; c < 8; ++c) q[c] = make_ulonglong2(acc[2*c], acc[2*c+1]);
}

// merge this thread's col (offset g*4 in each exporter slot) across 4 groups
__device__ __forceinline__ void mergeP(const ull* sRed, int quad, int g, ull m[4]) {
    m[0] = m[1] = m[2] = m[3] = 0ull;
#pragma unroll
    for (int gp = 0; gp < 4; ++gp) {
        const ull* p = sRed + (gp * 64 + quad) * SLOT + g * 4;
        ulonglong2 a = reinterpret_cast<const ulonglong2*>(p)[0];
        ulonglong2 b = reinterpret_cast<const ulonglong2*>(p)[1];
        m[0] = add2(m[0], a.x); m[1] = add2(m[1], a.y);
        m[2] = add2(m[2], b.x); m[3] = add2(m[3], b.y);
    }
}

// store 4 u64 slice to smem row (2 STS.128, stride 48B -> conflict-free)
__device__ __forceinline__ void st_slice(float* rowbase, const ull m[4]) {
    ulonglong2* p = reinterpret_cast<ulonglong2*>(rowbase);
    p[0] = make_ulonglong2(m[0], m[1]);
    p[1] = make_ulonglong2(m[2], m[3]);
}

// ---------------- merged transpose ----------------
__global__ void transpose_all(const float* __restrict__ wh,
                              const float* __restrict__ wout,
                              const float* __restrict__ wx) {
    __shared__ float tile[32][33];
    int b = blockIdx.x;
    const float* in; float* out; int rows, cols, bx;
    if (b < 64)       { in = wh;   out = g_whT;   rows = Hd; cols = Hd;  bx = b; }
    else if (b < 128) { in = wout; out = g_woutT; rows = Hd; cols = Hd;  bx = b - 64; }
    else              { in = wx;   out = g_wxT;   rows = Hd; cols = INd; bx = b - 128; }
    int nbx = cols / 32;
    int c0 = (bx % nbx) * 32, r0 = (bx / nbx) * 32;
    for (int dy = threadIdx.y; dy < 32; dy += 8)
        tile[dy][threadIdx.x] = in[(r0 + dy) * cols + (c0 + threadIdx.x)];
    __syncthreads();
    for (int dy = threadIdx.y; dy < 32; dy += 8)
        out[(c0 + dy) * rows + (r0 + threadIdx.x)] = tile[threadIdx.x][dy];
}

// ---------------- fused vector-field kernel (2 CTAs / SM) ----------------
__global__ void __launch_bounds__(NTHR, 2)
fused_kernel(const float* __restrict__ hin, const float* __restrict__ xin,
             const float* __restrict__ xdin, const float* __restrict__ b0,
             const float* __restrict__ b1, float* __restrict__ out) {
    extern __shared__ __align__(16) char smraw[];
    ull*   sRed = reinterpret_cast<ull*>(smraw);             // [256][SLOT]  36864B
    float* sA   = reinterpret_cast<float*>(sRed + NTHR * SLOT);  // [256][PITCH] 12288B
    float* sB   = sA + Hd * PITCH;                           // [256][PITCH] 12288B
    float* sXx  = sB + Hd * PITCH;                           // [64][PITCH]  3072B
    float* sXd  = sXx + INd * PITCH;                         // [64][PITCH]  3072B

    const int tid   = threadIdx.x;
    const int warp  = tid >> 5;
    const int lane  = tid & 31;
    const int g     = warp >> 1;                 // j-group 0..3 (warp-uniform)
    const int quad  = ((warp & 1) << 5) + lane;  // 0..63
    const int col0  = quad << 2;
    const int mycol = col0 + g;
    const int myrow = quad + (g << 6);           // phys(mycol)
    ull* myslot = sRed + (g * 64 + quad) * SLOT;
    const int row0  = blockIdx.x * ROWS;

    // ---- stage inputs (transposed + phys-permuted); no tail (2048 = 256*8)
    for (int e = tid; e < ROWS * Hd; e += NTHR) {
        int r = e >> 8, j = e & 255;
        int pr = (j >> 2) + ((j & 3) << 6);
        sA[pr * PITCH + r] = hin[(row0 + r) * Hd + j];
    }
    for (int e = tid; e < ROWS * INd; e += NTHR) {
        int r = e >> 6, i = e & 63;
        int pr = (i >> 2) + ((i & 3) << 4);
        sXx[pr * PITCH + r] = xin[(row0 + r) * INd + i];
        sXd[pr * PITCH + r] = xdin[(row0 + r) * INd + i];
    }
    __syncthreads();

    ull gate[4], dth[4], hd[4];
    ull acc[16];

    // ---- P1: l1 = x@wxT + h@whT + b0 -> gate, relu(sB)
#pragma unroll
    for (int q = 0; q < 16; ++q) acc[q] = 0ull;
    gemmC4<4, 16>(g_wxT, col0, g, sXx, acc);
    gemmC4<16, 64>(g_whT, col0, g, sA, acc);
    exportP(myslot, acc);
    __syncthreads();
    {
        ull m[4];
        mergeP(sRed, quad, g, m);
        float bk = b0[mycol];
        ull bp = pack2(bk, bk);
        ull relu[4];
#pragma unroll
        for (int t = 0; t < 4; ++t) {
            m[t] = add2(m[t], bp);
            float a, b; unpack2(m[t], a, b);
            float ga = (a > 0.f) ? 1.f : 0.f;
            float gb = (b > 0.f) ? 1.f : 0.f;
            gate[t] = pack2(ga, gb);
            relu[t] = pack2(ga * a, gb * b);
        }
        st_slice(sB + myrow * PITCH, relu);
    }
    __syncthreads();

    // ---- P2: uu = xdot@wxT ; gated-u -> sA
#pragma unroll
    for (int q = 0; q < 16; ++q) acc[q] = 0ull;
    gemmC4<4, 16>(g_wxT, col0, g, sXd, acc);
    exportP(myslot, acc);
    __syncthreads();
    {
        ull m[4];
        mergeP(sRed, quad, g, m);
#pragma unroll
        for (int t = 0; t < 4; ++t) m[t] = mul2(m[t], gate[t]);
        st_slice(sA + myrow * PITCH, m);
    }
    __syncthreads();

    // ---- P3: lout = relu@woutT + b1 -> dth (registers only)
#pragma unroll
    for (int q = 0; q < 16; ++q) acc[q] = 0ull;
    gemmC4<16, 64>(g_woutT, col0, g, sB, acc);
    exportP(myslot, acc);
    __syncthreads();
    {
        ull m[4];
        mergeP(sRed, quad, g, m);
        float bk = b1[mycol];
        ull bp = pack2(bk, bk);
#pragma unroll
        for (int t = 0; t < 4; ++t) {
            ull L = add2(m[t], bp);
            float a, b; unpack2(L, a, b);
            float ta = tanhf(a), tb = tanhf(b);
            dth[t] = pack2(1.f - ta * ta, 1.f - tb * tb);
        }
    }
    __syncthreads();

    // ---- P4: jx = gated-u@woutT ; curr = dth*jx -> sA ; hdot = curr
#pragma unroll
    for (int q = 0; q < 16; ++q) acc[q] = 0ull;
    gemmC4<16, 64>(g_woutT, col0, g, sA, acc);
    exportP(myslot, acc);
    __syncthreads();
    {
        ull m[4];
        mergeP(sRed, quad, g, m);
#pragma unroll
        for (int t = 0; t < 4; ++t) {
            m[t] = mul2(m[t], dth[t]);
            hd[t] = m[t];
        }
        st_slice(sA + myrow * PITCH, m);
    }
    __syncthreads();

    // ---- 8 Jh-power iterations: curr = dth * ((gate * (curr@whT)) @ woutT)
    for (int it = 0; it < KTERMS; ++it) {
#pragma unroll
        for (int q = 0; q < 16; ++q) acc[q] = 0ull;
        gemmC4<16, 64>(g_whT, col0, g, sA, acc);
        exportP(myslot, acc);
        __syncthreads();
        {
            ull m[4];
            mergeP(sRed, quad, g, m);
#pragma unroll
            for (int t = 0; t < 4; ++t) m[t] = mul2(m[t], gate[t]);
            st_slice(sB + myrow * PITCH, m);
        }
        __syncthreads();
#pragma unroll
        for (int q = 0; q < 16; ++q) acc[q] = 0ull;
        gemmC4<16, 64>(g_woutT, col0, g, sB, acc);
        exportP(myslot, acc);
        __syncthreads();
        {
            ull m[4];
            mergeP(sRed, quad, g, m);
#pragma unroll
            for (int t = 0; t < 4; ++t) {
                m[t] = mul2(m[t], dth[t]);
                hd[t] = add2(hd[t], m[t]);
            }
            st_slice(sA + myrow * PITCH, m);
        }
        __syncthreads();
    }

    // ---- write h_dot: thread owns (mycol, rows row0..row0+7)
#pragma unroll
    for (int t = 0; t < 4; ++t) {
        float a, b; unpack2(hd[t], a, b);
        out[(row0 + 2*t)     * Hd + mycol] = a;
        out[(row0 + 2*t + 1) * Hd + mycol] = b;
    }
}

#define SMEM_BYTES (NTHR * SLOT * 8 + (2 * Hd + 2 * INd) * PITCH * 4)

extern "C" void kernel_launch(void* const* d_in, const int* in_sizes, int n_in,
                              void* d_out, int out_size) {
    (void)in_sizes; (void)n_in; (void)out_size;
    const float* h_   = (const float*)d_in[0];
    const float* x    = (const float*)d_in[1];
    const float* xdot = (const float*)d_in[2];
    const float* wx   = (const float*)d_in[3];
    const float* wh   = (const float*)d_in[4];
    const float* wout = (const float*)d_in[5];
    const float* b0   = (const float*)d_in[6];
    const float* b1   = (const float*)d_in[7];
    float* out = (float*)d_out;

    cudaFuncSetAttribute(fused_kernel, cudaFuncAttributeMaxDynamicSharedMemorySize, SMEM_BYTES);
    transpose_all<<<144, dim3(32, 8)>>>(wh, wout, wx);
    fused_kernel<<<NCTAS, NTHR, SMEM_BYTES>>>(h_, x, xdot, b0, b1, out);
}